// round 1
// baseline (speedup 1.0000x reference)
#include <cuda_runtime.h>

#define BB 2048
#define NN 512
#define UU 64

// ---- block reduction helpers (256 threads, 8 warps) ----
__device__ __forceinline__ float blockReduceSum(float v, float* scratch) {
    #pragma unroll
    for (int o = 16; o; o >>= 1) v += __shfl_xor_sync(0xffffffffu, v, o);
    int w = threadIdx.x >> 5, l = threadIdx.x & 31;
    if (l == 0) scratch[w] = v;
    __syncthreads();
    if (threadIdx.x < 8) {
        v = scratch[threadIdx.x];
        #pragma unroll
        for (int o = 4; o; o >>= 1) v += __shfl_xor_sync(0x000000ffu, v, o);
        if (threadIdx.x == 0) scratch[0] = v;
    }
    __syncthreads();
    v = scratch[0];
    __syncthreads();
    return v;
}

__device__ __forceinline__ float blockReduceMax(float v, float* scratch) {
    #pragma unroll
    for (int o = 16; o; o >>= 1) v = fmaxf(v, __shfl_xor_sync(0xffffffffu, v, o));
    int w = threadIdx.x >> 5, l = threadIdx.x & 31;
    if (l == 0) scratch[w] = v;
    __syncthreads();
    if (threadIdx.x < 8) {
        v = scratch[threadIdx.x];
        #pragma unroll
        for (int o = 4; o; o >>= 1) v = fmaxf(v, __shfl_xor_sync(0x000000ffu, v, o));
        if (threadIdx.x == 0) scratch[0] = v;
    }
    __syncthreads();
    v = scratch[0];
    __syncthreads();
    return v;
}

__global__ __launch_bounds__(256) void ntm_kernel(
    const float* __restrict__ memory, const float* __restrict__ k,
    const float* __restrict__ beta_p, const float* __restrict__ g_p,
    const float* __restrict__ s,      const float* __restrict__ gamma_p,
    const float* __restrict__ w_pre,  const float* __restrict__ e,
    const float* __restrict__ a,
    float* __restrict__ out_w, float* __restrict__ out_r, float* __restrict__ out_m)
{
    __shared__ float arrA[NN];          // sim -> final w
    __shared__ float arrB[NN];          // wg (gated weights)
    __shared__ float k_sm[UU];
    __shared__ float rpart[16][UU];     // per-group partial r
    __shared__ float scratch[8];

    const int b    = blockIdx.x;
    const int tid  = threadIdx.x;
    const int gid  = tid >> 4;          // 16-lane group id, 0..15
    const int gl   = tid & 15;          // lane within group

    const float beta  = beta_p[0];
    const float gg    = g_p[0];
    const float gamma = gamma_p[0];
    const float s0 = s[b * 3 + 0], s1 = s[b * 3 + 1], s2 = s[b * 3 + 2];

    const float* memb  = memory + ((long)b << 15);   // b * N * U
    float*       outmb = out_m  + ((long)b << 15);

    // ---- load k, compute ||k|| ----
    if (tid < UU) k_sm[tid] = k[b * UU + tid];
    __syncthreads();
    float kv = (tid < UU) ? k_sm[tid] : 0.f;
    float ksq = blockReduceSum(kv * kv, scratch);
    const float ny = fmaxf(sqrtf(ksq), 1e-8f);

    const float4 k4 = *(const float4*)&k_sm[gl * 4];

    // ---- phase 1: cosine similarity per row ----
    #pragma unroll 4
    for (int it = 0; it < 32; ++it) {
        int row = it * 16 + gid;
        float4 m = *(const float4*)(memb + row * 64 + gl * 4);
        float d = m.x * k4.x + m.y * k4.y + m.z * k4.z + m.w * k4.w;
        float q = m.x * m.x + m.y * m.y + m.z * m.z + m.w * m.w;
        #pragma unroll
        for (int o = 8; o; o >>= 1) {
            d += __shfl_xor_sync(0xffffffffu, d, o);
            q += __shfl_xor_sync(0xffffffffu, q, o);
        }
        if (gl == 0) arrA[row] = d / (fmaxf(sqrtf(q), 1e-8f) * ny);
    }
    __syncthreads();

    // ---- phase 2: softmax, gate, circular shift, sharpen, normalize ----
    const int n0 = tid, n1 = tid + 256;
    float v0 = beta * arrA[n0];
    float v1 = beta * arrA[n1];
    float mx = blockReduceMax(fmaxf(v0, v1), scratch);
    float e0 = expf(v0 - mx);
    float e1 = expf(v1 - mx);
    float esum = blockReduceSum(e0 + e1, scratch);
    float einv = 1.f / esum;
    arrB[n0] = gg * e0 * einv + (1.f - gg) * w_pre[b * NN + n0];
    arrB[n1] = gg * e1 * einv + (1.f - gg) * w_pre[b * NN + n1];
    __syncthreads();

    float ws0 = s0 * arrB[(n0 + 511) & 511] + s1 * arrB[n0] + s2 * arrB[(n0 + 1) & 511];
    float ws1 = s0 * arrB[(n1 + 511) & 511] + s1 * arrB[n1] + s2 * arrB[(n1 + 1) & 511];
    float p0 = powf(ws0, gamma);
    float p1 = powf(ws1, gamma);
    float psum = blockReduceSum(p0 + p1, scratch);
    float pinv = 1.f / psum;
    float w0 = p0 * pinv + 1e-16f;
    float w1 = p1 * pinv + 1e-16f;
    arrA[n0] = w0;
    arrA[n1] = w1;
    out_w[b * NN + n0] = w0;
    out_w[b * NN + n1] = w1;
    __syncthreads();

    // ---- phase 3: fused read (r) + erase/add write (new_mem) ----
    const float4 e4 = *(const float4*)(e + b * UU + gl * 4);
    const float4 a4 = *(const float4*)(a + b * UU + gl * 4);
    float4 racc = make_float4(0.f, 0.f, 0.f, 0.f);
    #pragma unroll 4
    for (int it = 0; it < 32; ++it) {
        int row = it * 16 + gid;
        float4 m = *(const float4*)(memb + row * 64 + gl * 4);
        float wn = arrA[row];
        racc.x += wn * m.x;
        racc.y += wn * m.y;
        racc.z += wn * m.z;
        racc.w += wn * m.w;
        float4 nm;
        nm.x = m.x * (1.f - wn * e4.x) + wn * a4.x;
        nm.y = m.y * (1.f - wn * e4.y) + wn * a4.y;
        nm.z = m.z * (1.f - wn * e4.z) + wn * a4.z;
        nm.w = m.w * (1.f - wn * e4.w) + wn * a4.w;
        *(float4*)(outmb + row * 64 + gl * 4) = nm;
    }
    *(float4*)&rpart[gid][gl * 4] = racc;
    __syncthreads();
    if (tid < UU) {
        float rs = 0.f;
        #pragma unroll
        for (int gx = 0; gx < 16; ++gx) rs += rpart[gx][tid];
        out_r[b * UU + tid] = rs;
    }
}

extern "C" void kernel_launch(void* const* d_in, const int* in_sizes, int n_in,
                              void* d_out, int out_size) {
    const float* memory = (const float*)d_in[0];
    const float* k      = (const float*)d_in[1];
    const float* beta   = (const float*)d_in[2];
    const float* g      = (const float*)d_in[3];
    const float* s      = (const float*)d_in[4];
    const float* gamma  = (const float*)d_in[5];
    const float* w_pre  = (const float*)d_in[6];
    const float* e      = (const float*)d_in[7];
    const float* a      = (const float*)d_in[8];

    float* out   = (float*)d_out;
    float* out_w = out;                               // (B, N)
    float* out_r = out_w + (long)BB * NN;             // (B, U)
    float* out_m = out_r + (long)BB * UU;             // (B, N, U)

    ntm_kernel<<<BB, 256>>>(memory, k, beta, g, s, gamma, w_pre, e, a,
                            out_w, out_r, out_m);
}

// round 3
// speedup vs baseline: 1.2119x; 1.2119x over previous
#include <cuda_runtime.h>

#define BB 2048
#define NN 512
#define UU 64
#define NT 512   // threads per CTA (16 warps)

// ---- block reduction helpers (512 threads, 16 warps) ----
__device__ __forceinline__ float blockReduceSum(float v, float* scratch) {
    #pragma unroll
    for (int o = 16; o; o >>= 1) v += __shfl_xor_sync(0xffffffffu, v, o);
    int w = threadIdx.x >> 5, l = threadIdx.x & 31;
    if (l == 0) scratch[w] = v;
    __syncthreads();
    if (threadIdx.x < 16) {
        v = scratch[threadIdx.x];
        #pragma unroll
        for (int o = 8; o; o >>= 1) v += __shfl_xor_sync(0x0000ffffu, v, o);
        if (threadIdx.x == 0) scratch[0] = v;
    }
    __syncthreads();
    v = scratch[0];
    __syncthreads();
    return v;
}

__device__ __forceinline__ float blockReduceMax(float v, float* scratch) {
    #pragma unroll
    for (int o = 16; o; o >>= 1) v = fmaxf(v, __shfl_xor_sync(0xffffffffu, v, o));
    int w = threadIdx.x >> 5, l = threadIdx.x & 31;
    if (l == 0) scratch[w] = v;
    __syncthreads();
    if (threadIdx.x < 16) {
        v = scratch[threadIdx.x];
        #pragma unroll
        for (int o = 8; o; o >>= 1) v = fmaxf(v, __shfl_xor_sync(0x0000ffffu, v, o));
        if (threadIdx.x == 0) scratch[0] = v;
    }
    __syncthreads();
    v = scratch[0];
    __syncthreads();
    return v;
}

__global__ __launch_bounds__(NT, 1) void ntm_kernel(
    const float* __restrict__ memory, const float* __restrict__ k,
    const float* __restrict__ beta_p, const float* __restrict__ g_p,
    const float* __restrict__ s,      const float* __restrict__ gamma_p,
    const float* __restrict__ w_pre,  const float* __restrict__ e,
    const float* __restrict__ a,
    float* __restrict__ out_w, float* __restrict__ out_r, float* __restrict__ out_m)
{
    __shared__ float arrA[NN];          // sim -> final w
    __shared__ float arrB[NN];          // wg (gated weights)
    __shared__ float k_sm[UU];
    __shared__ float rpart[32][UU];     // per-group partial r (8 KB)
    __shared__ float scratch[16];

    const int b    = blockIdx.x;
    const int tid  = threadIdx.x;
    const int gid  = tid >> 4;          // 16-lane group id, 0..31
    const int gl   = tid & 15;          // lane within group

    const float beta  = beta_p[0];
    const float gg    = g_p[0];
    const float gamma = gamma_p[0];
    const float s0 = s[b * 3 + 0], s1 = s[b * 3 + 1], s2 = s[b * 3 + 2];

    const float* memb  = memory + ((long)b << 15);   // b * N * U
    float*       outmb = out_m  + ((long)b << 15);

    // ---- load k, compute ||k|| ----
    if (tid < UU) k_sm[tid] = k[b * UU + tid];
    __syncthreads();
    float kv = (tid < UU) ? k_sm[tid] : 0.f;
    float ksq = blockReduceSum(kv * kv, scratch);
    const float ny = fmaxf(sqrtf(ksq), 1e-8f);

    const float4 k4 = *(const float4*)&k_sm[gl * 4];

    // ---- phase 1: load ALL memory rows into registers (MLP=16), then sims ----
    // group gid owns rows gid + 32*i, i = 0..15; lane gl holds cols gl*4..gl*4+3
    float4 m4[16];
    #pragma unroll
    for (int i = 0; i < 16; ++i) {
        int row = gid + (i << 5);
        m4[i] = *(const float4*)(memb + row * 64 + gl * 4);
    }
    #pragma unroll
    for (int i = 0; i < 16; ++i) {
        float d = m4[i].x * k4.x + m4[i].y * k4.y + m4[i].z * k4.z + m4[i].w * k4.w;
        float q = m4[i].x * m4[i].x + m4[i].y * m4[i].y + m4[i].z * m4[i].z + m4[i].w * m4[i].w;
        #pragma unroll
        for (int o = 8; o; o >>= 1) {
            d += __shfl_xor_sync(0xffffffffu, d, o);
            q += __shfl_xor_sync(0xffffffffu, q, o);
        }
        if (gl == 0) arrA[gid + (i << 5)] = d / (fmaxf(sqrtf(q), 1e-8f) * ny);
    }
    __syncthreads();

    // ---- phase 2: softmax, gate, circular shift, sharpen, normalize ----
    float v0 = beta * arrA[tid];
    float mx = blockReduceMax(v0, scratch);
    float e0 = expf(v0 - mx);
    float esum = blockReduceSum(e0, scratch);
    arrB[tid] = gg * e0 / esum + (1.f - gg) * w_pre[b * NN + tid];
    __syncthreads();

    float ws0 = s0 * arrB[(tid + 511) & 511] + s1 * arrB[tid] + s2 * arrB[(tid + 1) & 511];
    // ws0 > 0 (convex combo of positive weights); pow via exp2/log2
    float p0 = exp2f(gamma * log2f(ws0));
    float psum = blockReduceSum(p0, scratch);
    float w0 = p0 / psum + 1e-16f;
    arrA[tid] = w0;
    out_w[b * NN + tid] = w0;
    __syncthreads();

    // ---- phase 3: fused read (r) + erase/add write (new_mem), all from regs ----
    const float4 e4 = *(const float4*)(e + b * UU + gl * 4);
    const float4 a4 = *(const float4*)(a + b * UU + gl * 4);
    float4 racc = make_float4(0.f, 0.f, 0.f, 0.f);
    #pragma unroll
    for (int i = 0; i < 16; ++i) {
        int row = gid + (i << 5);
        float wn = arrA[row];
        racc.x += wn * m4[i].x;
        racc.y += wn * m4[i].y;
        racc.z += wn * m4[i].z;
        racc.w += wn * m4[i].w;
        float4 nm;
        nm.x = m4[i].x * (1.f - wn * e4.x) + wn * a4.x;
        nm.y = m4[i].y * (1.f - wn * e4.y) + wn * a4.y;
        nm.z = m4[i].z * (1.f - wn * e4.z) + wn * a4.z;
        nm.w = m4[i].w * (1.f - wn * e4.w) + wn * a4.w;
        *(float4*)(outmb + row * 64 + gl * 4) = nm;
    }
    *(float4*)&rpart[gid][gl * 4] = racc;
    __syncthreads();
    if (tid < UU) {
        float rs = 0.f;
        #pragma unroll
        for (int gx = 0; gx < 32; ++gx) rs += rpart[gx][tid];
        out_r[b * UU + tid] = rs;
    }
}

extern "C" void kernel_launch(void* const* d_in, const int* in_sizes, int n_in,
                              void* d_out, int out_size) {
    const float* memory = (const float*)d_in[0];
    const float* k      = (const float*)d_in[1];
    const float* beta   = (const float*)d_in[2];
    const float* g      = (const float*)d_in[3];
    const float* s      = (const float*)d_in[4];
    const float* gamma  = (const float*)d_in[5];
    const float* w_pre  = (const float*)d_in[6];
    const float* e      = (const float*)d_in[7];
    const float* a      = (const float*)d_in[8];

    float* out   = (float*)d_out;
    float* out_w = out;                               // (B, N)
    float* out_r = out_w + (long)BB * NN;             // (B, U)
    float* out_m = out_r + (long)BB * UU;             // (B, N, U)

    ntm_kernel<<<BB, NT>>>(memory, k, beta, g, s, gamma, w_pre, e, a,
                           out_w, out_r, out_m);
}

// round 6
// speedup vs baseline: 1.2494x; 1.0310x over previous
#include <cuda_runtime.h>
#include <cstdint>

#define BB 2048
#define NN 512
#define UU 64
#define NT 1024   // threads per CTA (32 warps)

// dynamic smem layout (floats)
#define TILE_F   32768   // 512*64
#define SMEM_FLOATS (TILE_F + 512 + 512 + 64 + 4096 + 32)

__device__ __forceinline__ void cp_async16(float* smem_dst, const float* gsrc) {
    uint32_t s = (uint32_t)__cvta_generic_to_shared(smem_dst);
    asm volatile("cp.async.cg.shared.global [%0], [%1], 16;" :: "r"(s), "l"(gsrc));
}

// ---- block reductions (1024 threads, 32 warps) ----
__device__ __forceinline__ float blockReduceSum(float v, float* scratch) {
    #pragma unroll
    for (int o = 16; o; o >>= 1) v += __shfl_xor_sync(0xffffffffu, v, o);
    int w = threadIdx.x >> 5, l = threadIdx.x & 31;
    if (l == 0) scratch[w] = v;
    __syncthreads();
    if (threadIdx.x < 32) {
        v = scratch[threadIdx.x];
        #pragma unroll
        for (int o = 16; o; o >>= 1) v += __shfl_xor_sync(0xffffffffu, v, o);
        if (threadIdx.x == 0) scratch[0] = v;
    }
    __syncthreads();
    v = scratch[0];
    __syncthreads();
    return v;
}

__device__ __forceinline__ float blockReduceMax(float v, float* scratch) {
    #pragma unroll
    for (int o = 16; o; o >>= 1) v = fmaxf(v, __shfl_xor_sync(0xffffffffu, v, o));
    int w = threadIdx.x >> 5, l = threadIdx.x & 31;
    if (l == 0) scratch[w] = v;
    __syncthreads();
    if (threadIdx.x < 32) {
        v = scratch[threadIdx.x];
        #pragma unroll
        for (int o = 16; o; o >>= 1) v = fmaxf(v, __shfl_xor_sync(0xffffffffu, v, o));
        if (threadIdx.x == 0) scratch[0] = v;
    }
    __syncthreads();
    v = scratch[0];
    __syncthreads();
    return v;
}

__global__ __launch_bounds__(NT, 1) void ntm_kernel(
    const float* __restrict__ memory, const float* __restrict__ k,
    const float* __restrict__ beta_p, const float* __restrict__ g_p,
    const float* __restrict__ s,      const float* __restrict__ gamma_p,
    const float* __restrict__ w_pre,  const float* __restrict__ e,
    const float* __restrict__ a,
    float* __restrict__ out_w, float* __restrict__ out_r, float* __restrict__ out_m)
{
    extern __shared__ float dyn[];
    float* tile    = dyn;                 // 32768 floats (128 KB)
    float* arrA    = dyn + TILE_F;        // 512: sim -> final w
    float* arrB    = arrA + 512;          // 512: gated weights / r stage-2
    float* ksm     = arrB + 512;          // 64
    float* rpart   = ksm + 64;            // 4096: per-group partial r
    float* scratch = rpart + 4096;        // 32

    const int b   = blockIdx.x;
    const int tid = threadIdx.x;
    const int gid = tid >> 4;             // 16-lane group id, 0..63
    const int gl  = tid & 15;

    const float* memb  = memory + ((long)b << 15);
    float*       outmb = out_m  + ((long)b << 15);

    // ---- issue async tile loads: two halves ----
    #pragma unroll
    for (int i = 0; i < 4; ++i) {
        int j = tid + (i << 10);          // float4 index
        cp_async16(tile + j * 4, memb + j * 4);
    }
    asm volatile("cp.async.commit_group;");
    #pragma unroll
    for (int i = 4; i < 8; ++i) {
        int j = tid + (i << 10);
        cp_async16(tile + j * 4, memb + j * 4);
    }
    asm volatile("cp.async.commit_group;");

    // ---- k norm (overlaps the async loads; contains barriers) ----
    const float beta  = beta_p[0];
    const float gg    = g_p[0];
    const float gamma = gamma_p[0];
    const float s0 = s[b * 3 + 0], s1 = s[b * 3 + 1], s2 = s[b * 3 + 2];

    if (tid < UU) ksm[tid] = k[b * UU + tid];
    float kv = (tid < UU) ? k[b * UU + tid] : 0.f;
    float ksq = blockReduceSum(kv * kv, scratch);   // barriers publish ksm too
    const float ny = fmaxf(sqrtf(ksq), 1e-8f);
    const float4 k4 = *(const float4*)&ksm[gl * 4];

    // ---- phase 1: cosine sims, half 0 overlapped with half-1 load ----
    asm volatile("cp.async.wait_group 1;");
    __syncthreads();
    #pragma unroll
    for (int i = 0; i < 4; ++i) {
        int row = gid + (i << 6);         // rows 0..255
        float4 m = *(const float4*)(tile + row * 64 + gl * 4);
        float d = m.x * k4.x + m.y * k4.y + m.z * k4.z + m.w * k4.w;
        float q = m.x * m.x + m.y * m.y + m.z * m.z + m.w * m.w;
        #pragma unroll
        for (int o = 8; o; o >>= 1) {
            d += __shfl_xor_sync(0xffffffffu, d, o);
            q += __shfl_xor_sync(0xffffffffu, q, o);
        }
        if (gl == 0) arrA[row] = d / (fmaxf(sqrtf(q), 1e-8f) * ny);
    }
    asm volatile("cp.async.wait_group 0;");
    __syncthreads();
    #pragma unroll
    for (int i = 4; i < 8; ++i) {
        int row = gid + (i << 6);         // rows 256..511
        float4 m = *(const float4*)(tile + row * 64 + gl * 4);
        float d = m.x * k4.x + m.y * k4.y + m.z * k4.z + m.w * k4.w;
        float q = m.x * m.x + m.y * m.y + m.z * m.z + m.w * m.w;
        #pragma unroll
        for (int o = 8; o; o >>= 1) {
            d += __shfl_xor_sync(0xffffffffu, d, o);
            q += __shfl_xor_sync(0xffffffffu, q, o);
        }
        if (gl == 0) arrA[row] = d / (fmaxf(sqrtf(q), 1e-8f) * ny);
    }
    __syncthreads();

    // ---- phase 2: softmax, gate, shift, sharpen (tid<512 active) ----
    const float NEG_INF = __int_as_float(0xff800000);
    float v0 = (tid < NN) ? beta * arrA[tid] : NEG_INF;
    float mx = blockReduceMax(v0, scratch);
    float e0 = (tid < NN) ? expf(v0 - mx) : 0.f;
    float esum = blockReduceSum(e0, scratch);
    if (tid < NN)
        arrB[tid] = gg * e0 / esum + (1.f - gg) * w_pre[b * NN + tid];
    __syncthreads();

    float p0 = 0.f;
    if (tid < NN) {
        float ws0 = s0 * arrB[(tid + 511) & 511] + s1 * arrB[tid]
                  + s2 * arrB[(tid + 1) & 511];
        p0 = exp2f(gamma * log2f(ws0));   // ws0 > 0
    }
    float psum = blockReduceSum(p0, scratch);
    if (tid < NN) {
        float w0 = p0 / psum + 1e-16f;
        arrA[tid] = w0;
        out_w[b * NN + tid] = w0;
    }
    __syncthreads();

    // ---- phase 3: fused read + erase/add write, tile from smem ----
    const float4 e4 = *(const float4*)(e + b * UU + gl * 4);
    const float4 a4 = *(const float4*)(a + b * UU + gl * 4);
    float4 racc = make_float4(0.f, 0.f, 0.f, 0.f);
    #pragma unroll
    for (int i = 0; i < 8; ++i) {
        int row = gid + (i << 6);
        float4 m = *(const float4*)(tile + row * 64 + gl * 4);
        float wn = arrA[row];
        racc.x += wn * m.x;
        racc.y += wn * m.y;
        racc.z += wn * m.z;
        racc.w += wn * m.w;
        float4 nm;
        nm.x = m.x * (1.f - wn * e4.x) + wn * a4.x;
        nm.y = m.y * (1.f - wn * e4.y) + wn * a4.y;
        nm.z = m.z * (1.f - wn * e4.z) + wn * a4.z;
        nm.w = m.w * (1.f - wn * e4.w) + wn * a4.w;
        *(float4*)(outmb + row * 64 + gl * 4) = nm;
    }
    *(float4*)&rpart[gid * 64 + gl * 4] = racc;
    __syncthreads();

    // r reduction: 64 groups -> 8 -> 1
    if (tid < 512) {
        int col = tid & 63, h = tid >> 6;
        float sv = 0.f;
        #pragma unroll
        for (int r2 = 0; r2 < 8; ++r2) sv += rpart[(h * 8 + r2) * 64 + col];
        arrB[h * 64 + col] = sv;
    }
    __syncthreads();
    if (tid < UU) {
        float rs = 0.f;
        #pragma unroll
        for (int i2 = 0; i2 < 8; ++i2) rs += arrB[i2 * 64 + tid];
        out_r[b * UU + tid] = rs;
    }
}

extern "C" void kernel_launch(void* const* d_in, const int* in_sizes, int n_in,
                              void* d_out, int out_size) {
    const float* memory = (const float*)d_in[0];
    const float* k      = (const float*)d_in[1];
    const float* beta   = (const float*)d_in[2];
    const float* g      = (const float*)d_in[3];
    const float* s      = (const float*)d_in[4];
    const float* gamma  = (const float*)d_in[5];
    const float* w_pre  = (const float*)d_in[6];
    const float* e      = (const float*)d_in[7];
    const float* a      = (const float*)d_in[8];

    float* out   = (float*)d_out;
    float* out_w = out;                               // (B, N)
    float* out_r = out_w + (long)BB * NN;             // (B, U)
    float* out_m = out_r + (long)BB * UU;             // (B, N, U)

    const int smem_bytes = SMEM_FLOATS * sizeof(float);
    cudaFuncSetAttribute(ntm_kernel,
                         cudaFuncAttributeMaxDynamicSharedMemorySize,
                         smem_bytes);

    ntm_kernel<<<BB, NT, smem_bytes>>>(memory, k, beta, g, s, gamma, w_pre, e, a,
                                       out_w, out_r, out_m);
}